// round 9
// baseline (speedup 1.0000x reference)
#include <cuda_runtime.h>
#include <cuda_pipeline.h>
#include <mma.h>
#include <math.h>

using namespace nvcuda;

// Problem constants
#define TT    256
#define BSZ   64
#define DIN   1024
#define HIDN  1024
#define NL    2
#define H4    (4 * HIDN)
#define MTOT  (TT * BSZ)          // 16384
#define BH    (BSZ * HIDN)        // 65536

#define NCTA  128                 // persistent CTAs, 1 per SM
#define UPC   8                   // hidden units per CTA; 32 gate-cols per CTA
#define NTHR  512                 // 16 warps: 2 K-halves x 4 batch-tiles x 2 col-tiles

// ---------------- device scratch (no allocations allowed) ----------------
__device__ float g_Xp[(size_t)MTOT * H4];   // precomputed x@Wx^T + b
__device__ float g_H0[(size_t)MTOT * HIDN]; // layer-0 hidden outputs
__device__ float g_c[NL][BH];               // final cell states
__device__ unsigned g_flags[NCTA];          // per-CTA barrier flags

__global__ void reset_flags_kernel() {
    if (threadIdx.x < NCTA) g_flags[threadIdx.x] = 0u;
}

// ---------------- precompute GEMM: C = A[M,K] @ W[N,K]^T + bias[N] -> g_Xp ----------------
// 128x64 block tile, 256 threads (8 warps: 4m x 2n, each 32x32), K-chunk 32,
// double-buffered cp.async staging.
#define GX_BUF_FLOATS ((128 + 64) * 36)

__global__ void __launch_bounds__(256, 2)
gemm_xp_kernel(const float* __restrict__ A,
               const float* __restrict__ W,
               const float* __restrict__ bias,
               int M, int N, int K) {
    extern __shared__ float gsm[];

    const int tid  = threadIdx.x;
    const int warp = tid >> 5;
    const int wm   = warp & 3;
    const int wn   = warp >> 2;
    const int row0A = blockIdx.y * 128;
    const int row0W = blockIdx.x * 64;

    wmma::fragment<wmma::accumulator, 16, 16, 8, float> acc[2][2];
#pragma unroll
    for (int i = 0; i < 2; i++)
#pragma unroll
        for (int j = 0; j < 2; j++) wmma::fill_fragment(acc[i][j], 0.f);

    const int nchunks = K / 32;

#define GX_STAGE(buf, kt)                                                          \
    {                                                                              \
        float* As_ = gsm + (buf) * GX_BUF_FLOATS;                                  \
        float* Ws_ = As_ + 128 * 36;                                               \
        int k0_ = (kt) * 32;                                                       \
        _Pragma("unroll")                                                          \
        for (int i_ = 0; i_ < 4; i_++) {                                           \
            int e_ = tid + i_ * 256;                                               \
            int r_ = e_ >> 3, c4_ = (e_ & 7) * 4;                                  \
            __pipeline_memcpy_async(&As_[r_ * 36 + c4_],                           \
                A + (size_t)(row0A + r_) * K + k0_ + c4_, 16);                     \
        }                                                                          \
        _Pragma("unroll")                                                          \
        for (int i_ = 0; i_ < 2; i_++) {                                           \
            int e_ = tid + i_ * 256;                                               \
            int r_ = e_ >> 3, c4_ = (e_ & 7) * 4;                                  \
            __pipeline_memcpy_async(&Ws_[r_ * 36 + c4_],                           \
                W + (size_t)(row0W + r_) * K + k0_ + c4_, 16);                     \
        }                                                                          \
    }

    GX_STAGE(0, 0);
    __pipeline_commit();

    for (int kt = 0; kt < nchunks; kt++) {
        int cur = kt & 1;
        __pipeline_wait_prior(0);
        __syncthreads();
        if (kt + 1 < nchunks) {
            GX_STAGE(cur ^ 1, kt + 1);
            __pipeline_commit();
        }
        float* As_ = gsm + cur * GX_BUF_FLOATS;
        float* Ws_ = As_ + 128 * 36;
#pragma unroll
        for (int kk = 0; kk < 32; kk += 8) {
            wmma::fragment<wmma::matrix_a, 16, 16, 8, wmma::precision::tf32, wmma::row_major> af[2];
            wmma::fragment<wmma::matrix_b, 16, 16, 8, wmma::precision::tf32, wmma::col_major> bf[2];
#pragma unroll
            for (int i = 0; i < 2; i++) {
                wmma::load_matrix_sync(af[i], &As_[(wm * 32 + i * 16) * 36 + kk], 36);
#pragma unroll
                for (int e = 0; e < af[i].num_elements; e++) af[i].x[e] = wmma::__float_to_tf32(af[i].x[e]);
            }
#pragma unroll
            for (int j = 0; j < 2; j++) {
                wmma::load_matrix_sync(bf[j], &Ws_[(wn * 32 + j * 16) * 36 + kk], 36);
#pragma unroll
                for (int e = 0; e < bf[j].num_elements; e++) bf[j].x[e] = wmma::__float_to_tf32(bf[j].x[e]);
            }
#pragma unroll
            for (int i = 0; i < 2; i++)
#pragma unroll
                for (int j = 0; j < 2; j++)
                    wmma::mma_sync(acc[i][j], af[i], bf[j], acc[i][j]);
        }
        __syncthreads();
    }

    float* Cs = gsm;
    __syncthreads();
#pragma unroll
    for (int i = 0; i < 2; i++)
#pragma unroll
        for (int j = 0; j < 2; j++)
            wmma::store_matrix_sync(&Cs[(wm * 32 + i * 16) * 68 + wn * 32 + j * 16],
                                    acc[i][j], 68, wmma::mem_row_major);
    __syncthreads();

    for (int idx = tid; idx < 128 * 64; idx += 256) {
        int r = idx >> 6, c = idx & 63;
        g_Xp[(size_t)(row0A + r) * N + row0W + c] = Cs[r * 68 + c] + bias[row0W + c];
    }
#undef GX_STAGE
}

// ---------------- persistent recurrence ----------------
// 128 CTAs x 512 threads. CTA owns 8 hidden units (32 gate-cols). Wh slice in
// SMEM (132 KB, loaded once). h(t-1) staged per step as 8 chunks of K=128 via
// cp.async double buffer, chunk order ROTATED by blockIdx to de-correlate the
// 128 CTAs' L2 streams. Flag-array grid barrier (release store / acquire poll).
//
// SMEM floats:
//   Ws : 32 x 1032                = 33024
//   Hs : 2 x (64 x 132)           = 16896
//   Gs : 64 x 72                  =  4608
//   cs : 512                      =   512
#define SM_WS 0
#define SM_HS (SM_WS + 32 * 1032)
#define SM_GS (SM_HS + 2 * 64 * 132)
#define SM_CS (SM_GS + 64 * 72)
#define SM_FLOATS (SM_CS + 512)

__global__ void __launch_bounds__(NTHR, 1)
lstm_seq_kernel(const float* __restrict__ Wh,   // [H4, HIDN] layer base
                const float* __restrict__ Xp,   // [TT, BSZ, H4]
                float* Htraj,                   // [TT, BSZ, HIDN]
                float* __restrict__ gC) {       // [BSZ, HIDN] final cell out
    extern __shared__ float sm[];
    float* Ws = sm + SM_WS;
    float* Hs = sm + SM_HS;
    float* Gs = sm + SM_GS;
    float* cs = sm + SM_CS;

    const int tid  = threadIdx.x;
    const int warp = tid >> 5;
    const int wk   = warp >> 3;        // 0..1 K-half of each 128 chunk
    const int wm   = (warp >> 1) & 3;  // 0..3 batch tile
    const int wn   = warp & 1;         // 0..1 col tile
    const int bid  = blockIdx.x;
    const int j0   = bid * UPC;

    // ---- preload Wh slice: smem row n (0..31) = gate (n>>3), unit (n&7) ----
    for (int i4 = tid; i4 < 32 * 256; i4 += NTHR) {
        int n  = i4 >> 8;
        int c4 = (i4 & 255) * 4;
        int row = (n >> 3) * HIDN + j0 + (n & 7);
        *(float4*)&Ws[n * 1032 + c4] = *(const float4*)(Wh + (size_t)row * HIDN + c4);
    }
    cs[tid] = 0.f;
    __syncthreads();

    // staging mapping: chunk = 64 rows x 32 float4; 512 threads -> 4 float4 each
    const int srow = tid >> 3;
    const int sc4  = (tid & 7) * 4;

    // epilogue mapping
    const int eb = tid >> 3;
    const int eu = tid & 7;

    const float* Ws_warp = Ws + (size_t)(wn * 16) * 1032;

    // barrier poll slots for warp 0 (4 per lane)
    const int lane = tid & 31;

    // x prefetch for t=0
    float x_i, x_f, x_o, x_c;
    {
        const float* xb = Xp + (size_t)eb * H4 + j0 + eu;
        x_i = xb[0]; x_f = xb[HIDN]; x_o = xb[2 * HIDN]; x_c = xb[3 * HIDN];
    }

    for (int t = 0; t < TT; t++) {
        wmma::fragment<wmma::accumulator, 16, 16, 8, float> acc[2];
        wmma::fill_fragment(acc[0], 0.f);
        wmma::fill_fragment(acc[1], 0.f);

        if (t > 0) {
            const float* Hprev = Htraj + (size_t)(t - 1) * BH;

#define H_STAGE(buf, chunk)                                                       \
            {                                                                     \
                float* Hb_ = Hs + (buf) * (64 * 132);                             \
                int k0_ = (chunk) * 128;                                          \
                _Pragma("unroll")                                                 \
                for (int p_ = 0; p_ < 4; p_++)                                    \
                    __pipeline_memcpy_async(&Hb_[srow * 132 + p_ * 32 + sc4],     \
                        Hprev + (size_t)srow * HIDN + k0_ + p_ * 32 + sc4, 16);   \
            }

            int pc0 = bid & 7;
            H_STAGE(0, pc0);
            __pipeline_commit();

            for (int it = 0; it < 8; it++) {
                int cur = it & 1;
                int pc  = (it + bid) & 7;       // this iteration's chunk
                __pipeline_wait_prior(0);
                __syncthreads();
                if (it < 7) {
                    int pn = (it + 1 + bid) & 7;
                    H_STAGE(cur ^ 1, pn);
                    __pipeline_commit();
                }
                const float* Hb = Hs + cur * (64 * 132);
                const float* Wb = Ws_warp + pc * 128 + wk * 64;
                const float* Ab = Hb + (wm * 16) * 132 + wk * 64;
#pragma unroll
                for (int kk = 0; kk < 64; kk += 8) {
                    wmma::fragment<wmma::matrix_a, 16, 16, 8, wmma::precision::tf32, wmma::row_major> af;
                    wmma::load_matrix_sync(af, Ab + kk, 132);
#pragma unroll
                    for (int i = 0; i < af.num_elements; i++) af.x[i] = wmma::__float_to_tf32(af.x[i]);
                    wmma::fragment<wmma::matrix_b, 16, 16, 8, wmma::precision::tf32, wmma::col_major> bf;
                    wmma::load_matrix_sync(bf, Wb + kk, 1032);
#pragma unroll
                    for (int i = 0; i < bf.num_elements; i++) bf.x[i] = wmma::__float_to_tf32(bf.x[i]);
                    wmma::mma_sync(acc[(kk >> 3) & 1], af, bf, acc[(kk >> 3) & 1]);
                }
            }
            __syncthreads();
#undef H_STAGE
        }

        // sum local accumulators; store K-half partial
#pragma unroll
        for (int i = 0; i < acc[0].num_elements; i++) acc[0].x[i] += acc[1].x[i];
        wmma::store_matrix_sync(&Gs[(wm * 16) * 72 + wk * 36 + wn * 16], acc[0], 72,
                                wmma::mem_row_major);
        __syncthreads();

        // ---- LSTM cell epilogue ----
        {
            float gi = Gs[eb * 72 + eu]      + Gs[eb * 72 + 36 + eu]      + x_i;
            float gf = Gs[eb * 72 + 8 + eu]  + Gs[eb * 72 + 36 + 8 + eu]  + x_f;
            float go = Gs[eb * 72 + 16 + eu] + Gs[eb * 72 + 36 + 16 + eu] + x_o;
            float gc = Gs[eb * 72 + 24 + eu] + Gs[eb * 72 + 36 + 24 + eu] + x_c;
            float si = 1.f / (1.f + expf(-gi));
            float sf = 1.f / (1.f + expf(-gf));
            float so = 1.f / (1.f + expf(-go));
            float cn = sf * cs[tid] + si * tanhf(gc);
            cs[tid] = cn;
            Htraj[(size_t)t * BH + (size_t)eb * HIDN + j0 + eu] = so * tanhf(cn);
        }

        // prefetch next step's x (overlaps the barrier)
        if (t + 1 < TT) {
            const float* xb = Xp + (size_t)(t + 1) * BSZ * H4 + (size_t)eb * H4 + j0 + eu;
            x_i = xb[0]; x_f = xb[HIDN]; x_o = xb[2 * HIDN]; x_c = xb[3 * HIDN];
        }

        // ---- flag-array grid barrier ----
        __syncthreads();
        if (warp == 0) {
            unsigned target = (unsigned)(t + 1);
            if (lane == 0) {
                asm volatile("st.release.gpu.global.u32 [%0], %1;"
                             :: "l"(&g_flags[bid]), "r"(target) : "memory");
            }
            bool done = false;
            do {
                unsigned v0, v1, v2, v3;
                asm volatile("ld.acquire.gpu.global.u32 %0, [%1];"
                             : "=r"(v0) : "l"(&g_flags[lane]) : "memory");
                asm volatile("ld.acquire.gpu.global.u32 %0, [%1];"
                             : "=r"(v1) : "l"(&g_flags[lane + 32]) : "memory");
                asm volatile("ld.acquire.gpu.global.u32 %0, [%1];"
                             : "=r"(v2) : "l"(&g_flags[lane + 64]) : "memory");
                asm volatile("ld.acquire.gpu.global.u32 %0, [%1];"
                             : "=r"(v3) : "l"(&g_flags[lane + 96]) : "memory");
                done = (v0 >= target) && (v1 >= target) && (v2 >= target) && (v3 >= target);
                done = __all_sync(0xffffffffu, done);
            } while (!done);
        }
        __syncthreads();
    }

    // ---- final cell state ----
    gC[(size_t)eb * HIDN + j0 + eu] = cs[tid];
}

// ---------------- finalize: Hf / Cf ----------------
__global__ void finalize_kernel(const float* __restrict__ h0_last,
                                const float* __restrict__ h1_last,
                                float* __restrict__ Hf,
                                float* __restrict__ Cf) {
    int i = blockIdx.x * blockDim.x + threadIdx.x;
    if (i < BH) {
        Hf[i]      = h0_last[i];
        Hf[BH + i] = h1_last[i];
        Cf[i]      = g_c[0][i];
        Cf[BH + i] = g_c[1][i];
    }
}

// ---------------- launch ----------------
extern "C" void kernel_launch(void* const* d_in, const int* in_sizes, int n_in,
                              void* d_out, int out_size) {
    const float* X    = (const float*)d_in[0]; // [T, B, D]
    const float* Wx   = (const float*)d_in[1]; // [L, 4H, D]
    const float* Wh   = (const float*)d_in[2]; // [L, 4H, H]
    const float* bias = (const float*)d_in[3]; // [L, 4H]

    float* out     = (float*)d_out;
    float* outputs = out;                              // [T, B, H]
    float* Hf      = out + (size_t)TT * BSZ * HIDN;
    float* Cf      = Hf + (size_t)NL * BH;

    float *Xp_p = nullptr, *H0_p = nullptr, *gc_p = nullptr;
    cudaGetSymbolAddress((void**)&Xp_p, g_Xp);
    cudaGetSymbolAddress((void**)&H0_p, g_H0);
    cudaGetSymbolAddress((void**)&gc_p, g_c);

    static bool attr_set = false;
    if (!attr_set) {
        cudaFuncSetAttribute(lstm_seq_kernel,
                             cudaFuncAttributeMaxDynamicSharedMemorySize,
                             SM_FLOATS * sizeof(float));
        cudaFuncSetAttribute(gemm_xp_kernel,
                             cudaFuncAttributeMaxDynamicSharedMemorySize,
                             2 * GX_BUF_FLOATS * sizeof(float));
        attr_set = true;
    }

    dim3 gg(H4 / 64, MTOT / 128);
    size_t gx_smem = 2 * GX_BUF_FLOATS * sizeof(float);

    // Launch-order shim: extra leading launch so ncu's fixed -s index lands on
    // lstm_seq_kernel (diagnostic for the next round). Also resets flags.
    reset_flags_kernel<<<1, NCTA>>>();

    // Layer 0
    gemm_xp_kernel<<<gg, 256, gx_smem>>>(X, Wx, bias, MTOT, H4, DIN);
    reset_flags_kernel<<<1, NCTA>>>();
    lstm_seq_kernel<<<NCTA, NTHR, SM_FLOATS * sizeof(float)>>>(
        Wh, Xp_p, H0_p, gc_p);

    // Layer 1
    gemm_xp_kernel<<<gg, 256, gx_smem>>>(H0_p, Wx + (size_t)H4 * DIN, bias + H4, MTOT, H4, HIDN);
    reset_flags_kernel<<<1, NCTA>>>();
    lstm_seq_kernel<<<NCTA, NTHR, SM_FLOATS * sizeof(float)>>>(
        Wh + (size_t)H4 * HIDN, Xp_p, outputs, gc_p + BH);

    finalize_kernel<<<(BH + 255) / 256, 256>>>(
        H0_p + (size_t)(TT - 1) * BH,
        outputs + (size_t)(TT - 1) * BH,
        Hf, Cf);
}

// round 10
// speedup vs baseline: 1.0515x; 1.0515x over previous
#include <cuda_runtime.h>
#include <cuda_pipeline.h>
#include <mma.h>
#include <math.h>

using namespace nvcuda;

// Problem constants
#define TT    256
#define BSZ   64
#define DIN   1024
#define HIDN  1024
#define NL    2
#define H4    (4 * HIDN)
#define MTOT  (TT * BSZ)          // 16384
#define BH    (BSZ * HIDN)        // 65536

#define NCTA  128                 // persistent CTAs, 1 per SM
#define UPC   8                   // hidden units per CTA; 32 gate-cols per CTA
#define NTHR  512                 // 16 warps: 2 K-halves x 4 batch-tiles x 2 col-tiles
#define NCHUNK 8                  // K chunks of 128 per step
#define PROD_PER_CHUNK 16         // CTAs producing each 128-unit chunk

// ---------------- device scratch (no allocations allowed) ----------------
__device__ float g_Xp[(size_t)MTOT * H4];   // precomputed x@Wx^T + b
__device__ float g_H0[(size_t)MTOT * HIDN]; // layer-0 hidden outputs
__device__ float g_c[NL][BH];               // final cell states
__device__ unsigned g_cnt[TT * NCHUNK];     // per-(t,chunk) producer counters

__global__ void reset_cnt_kernel() {
    int i = blockIdx.x * blockDim.x + threadIdx.x;
    if (i < TT * NCHUNK) g_cnt[i] = 0u;
}

// ---------------- precompute GEMM: C = A[M,K] @ W[N,K]^T + bias[N] -> g_Xp ----------------
// 128x64 block tile, 256 threads (8 warps: 4m x 2n, each 32x32), K-chunk 32,
// double-buffered cp.async staging. (unchanged from R8)
#define GX_BUF_FLOATS ((128 + 64) * 36)

__global__ void __launch_bounds__(256, 2)
gemm_xp_kernel(const float* __restrict__ A,
               const float* __restrict__ W,
               const float* __restrict__ bias,
               int M, int N, int K) {
    extern __shared__ float gsm[];

    const int tid  = threadIdx.x;
    const int warp = tid >> 5;
    const int wm   = warp & 3;
    const int wn   = warp >> 2;
    const int row0A = blockIdx.y * 128;
    const int row0W = blockIdx.x * 64;

    wmma::fragment<wmma::accumulator, 16, 16, 8, float> acc[2][2];
#pragma unroll
    for (int i = 0; i < 2; i++)
#pragma unroll
        for (int j = 0; j < 2; j++) wmma::fill_fragment(acc[i][j], 0.f);

    const int nchunks = K / 32;

#define GX_STAGE(buf, kt)                                                          \
    {                                                                              \
        float* As_ = gsm + (buf) * GX_BUF_FLOATS;                                  \
        float* Ws_ = As_ + 128 * 36;                                               \
        int k0_ = (kt) * 32;                                                       \
        _Pragma("unroll")                                                          \
        for (int i_ = 0; i_ < 4; i_++) {                                           \
            int e_ = tid + i_ * 256;                                               \
            int r_ = e_ >> 3, c4_ = (e_ & 7) * 4;                                  \
            __pipeline_memcpy_async(&As_[r_ * 36 + c4_],                           \
                A + (size_t)(row0A + r_) * K + k0_ + c4_, 16);                     \
        }                                                                          \
        _Pragma("unroll")                                                          \
        for (int i_ = 0; i_ < 2; i_++) {                                           \
            int e_ = tid + i_ * 256;                                               \
            int r_ = e_ >> 3, c4_ = (e_ & 7) * 4;                                  \
            __pipeline_memcpy_async(&Ws_[r_ * 36 + c4_],                           \
                W + (size_t)(row0W + r_) * K + k0_ + c4_, 16);                     \
        }                                                                          \
    }

    GX_STAGE(0, 0);
    __pipeline_commit();

    for (int kt = 0; kt < nchunks; kt++) {
        int cur = kt & 1;
        __pipeline_wait_prior(0);
        __syncthreads();
        if (kt + 1 < nchunks) {
            GX_STAGE(cur ^ 1, kt + 1);
            __pipeline_commit();
        }
        float* As_ = gsm + cur * GX_BUF_FLOATS;
        float* Ws_ = As_ + 128 * 36;
#pragma unroll
        for (int kk = 0; kk < 32; kk += 8) {
            wmma::fragment<wmma::matrix_a, 16, 16, 8, wmma::precision::tf32, wmma::row_major> af[2];
            wmma::fragment<wmma::matrix_b, 16, 16, 8, wmma::precision::tf32, wmma::col_major> bf[2];
#pragma unroll
            for (int i = 0; i < 2; i++) {
                wmma::load_matrix_sync(af[i], &As_[(wm * 32 + i * 16) * 36 + kk], 36);
#pragma unroll
                for (int e = 0; e < af[i].num_elements; e++) af[i].x[e] = wmma::__float_to_tf32(af[i].x[e]);
            }
#pragma unroll
            for (int j = 0; j < 2; j++) {
                wmma::load_matrix_sync(bf[j], &Ws_[(wn * 32 + j * 16) * 36 + kk], 36);
#pragma unroll
                for (int e = 0; e < bf[j].num_elements; e++) bf[j].x[e] = wmma::__float_to_tf32(bf[j].x[e]);
            }
#pragma unroll
            for (int i = 0; i < 2; i++)
#pragma unroll
                for (int j = 0; j < 2; j++)
                    wmma::mma_sync(acc[i][j], af[i], bf[j], acc[i][j]);
        }
        __syncthreads();
    }

    float* Cs = gsm;
    __syncthreads();
#pragma unroll
    for (int i = 0; i < 2; i++)
#pragma unroll
        for (int j = 0; j < 2; j++)
            wmma::store_matrix_sync(&Cs[(wm * 32 + i * 16) * 68 + wn * 32 + j * 16],
                                    acc[i][j], 68, wmma::mem_row_major);
    __syncthreads();

    for (int idx = tid; idx < 128 * 64; idx += 256) {
        int r = idx >> 6, c = idx & 63;
        g_Xp[(size_t)(row0A + r) * N + row0W + c] = Cs[r * 68 + c] + bias[row0W + c];
    }
#undef GX_STAGE
}

// ---------------- persistent recurrence, barrier-free dataflow ----------------
// 128 CTAs x 512 threads. CTA bid owns units [bid*8, bid*8+8) (32 gate-cols);
// those units lie in K-chunk (bid>>4). Wh slice SMEM-resident (132 KB).
// Per step: consume h(t-1) in 8 cp.async-staged chunks, order rotated by bid.
// Before staging chunk c, wait (acquire) until its 16 producer CTAs have
// released cnt[t-1][c] to 16. After writing h(t), release-increment
// cnt[t][bid>>4]. NO grid barrier anywhere.
//
// SMEM floats:
//   Ws : 32 x 1032                = 33024
//   Hs : 2 x (64 x 132)           = 16896
//   Gs : 64 x 72                  =  4608
//   cs : 512                      =   512
#define SM_WS 0
#define SM_HS (SM_WS + 32 * 1032)
#define SM_GS (SM_HS + 2 * 64 * 132)
#define SM_CS (SM_GS + 64 * 72)
#define SM_FLOATS (SM_CS + 512)

__global__ void __launch_bounds__(NTHR, 1)
lstm_seq_kernel(const float* __restrict__ Wh,   // [H4, HIDN] layer base
                const float* __restrict__ Xp,   // [TT, BSZ, H4]
                float* Htraj,                   // [TT, BSZ, HIDN]
                float* __restrict__ gC) {       // [BSZ, HIDN] final cell out
    extern __shared__ float sm[];
    float* Ws = sm + SM_WS;
    float* Hs = sm + SM_HS;
    float* Gs = sm + SM_GS;
    float* cs = sm + SM_CS;

    const int tid  = threadIdx.x;
    const int warp = tid >> 5;
    const int wk   = warp >> 3;        // 0..1 K-half of each 128 chunk
    const int wm   = (warp >> 1) & 3;  // 0..3 batch tile
    const int wn   = warp & 1;         // 0..1 col tile
    const int bid  = blockIdx.x;
    const int j0   = bid * UPC;
    const int mychunk = bid >> 4;      // chunk this CTA's h units belong to

    // ---- preload Wh slice: smem row n (0..31) = gate (n>>3), unit (n&7) ----
    for (int i4 = tid; i4 < 32 * 256; i4 += NTHR) {
        int n  = i4 >> 8;
        int c4 = (i4 & 255) * 4;
        int row = (n >> 3) * HIDN + j0 + (n & 7);
        *(float4*)&Ws[n * 1032 + c4] = *(const float4*)(Wh + (size_t)row * HIDN + c4);
    }
    cs[tid] = 0.f;
    __syncthreads();

    // staging mapping: chunk = 64 rows x 32 float4; 512 threads -> 4 float4 each
    const int srow = tid >> 3;
    const int sc4  = (tid & 7) * 4;

    // epilogue mapping
    const int eb = tid >> 3;
    const int eu = tid & 7;

    const float* Ws_warp = Ws + (size_t)(wn * 16) * 1032;

    // x prefetch for t=0
    float x_i, x_f, x_o, x_c;
    {
        const float* xb = Xp + (size_t)eb * H4 + j0 + eu;
        x_i = xb[0]; x_f = xb[HIDN]; x_o = xb[2 * HIDN]; x_c = xb[3 * HIDN];
    }

    for (int t = 0; t < TT; t++) {
        wmma::fragment<wmma::accumulator, 16, 16, 8, float> acc[2];
        wmma::fill_fragment(acc[0], 0.f);
        wmma::fill_fragment(acc[1], 0.f);

        if (t > 0) {
            const float* Hprev = Htraj + (size_t)(t - 1) * BH;
            const unsigned* cnt_prev = g_cnt + (t - 1) * NCHUNK;

#define H_STAGE(buf, chunk)                                                       \
            {                                                                     \
                float* Hb_ = Hs + (buf) * (64 * 132);                             \
                int k0_ = (chunk) * 128;                                          \
                _Pragma("unroll")                                                 \
                for (int p_ = 0; p_ < 4; p_++)                                    \
                    __pipeline_memcpy_async(&Hb_[srow * 132 + p_ * 32 + sc4],     \
                        Hprev + (size_t)srow * HIDN + k0_ + p_ * 32 + sc4, 16);   \
            }
#define CHUNK_WAIT(c)                                                             \
            if (tid == 0) {                                                       \
                unsigned v_;                                                      \
                do {                                                              \
                    asm volatile("ld.acquire.gpu.global.u32 %0, [%1];"            \
                                 : "=r"(v_) : "l"(cnt_prev + (c)) : "memory");    \
                } while (v_ < PROD_PER_CHUNK);                                    \
            }

            int pc0 = bid & 7;
            CHUNK_WAIT(pc0);
            __syncthreads();
            H_STAGE(0, pc0);
            __pipeline_commit();

            for (int it = 0; it < NCHUNK; it++) {
                int cur = it & 1;
                int pc  = (it + bid) & 7;
                int pn  = (it + 1 + bid) & 7;
                if (it < NCHUNK - 1) { CHUNK_WAIT(pn); }  // overlaps in-flight cp.async
                __pipeline_wait_prior(0);
                __syncthreads();
                if (it < NCHUNK - 1) {
                    H_STAGE(cur ^ 1, pn);
                    __pipeline_commit();
                }
                const float* Hb = Hs + cur * (64 * 132);
                const float* Wb = Ws_warp + pc * 128 + wk * 64;
                const float* Ab = Hb + (wm * 16) * 132 + wk * 64;
#pragma unroll
                for (int kk = 0; kk < 64; kk += 8) {
                    wmma::fragment<wmma::matrix_a, 16, 16, 8, wmma::precision::tf32, wmma::row_major> af;
                    wmma::load_matrix_sync(af, Ab + kk, 132);
#pragma unroll
                    for (int i = 0; i < af.num_elements; i++) af.x[i] = wmma::__float_to_tf32(af.x[i]);
                    wmma::fragment<wmma::matrix_b, 16, 16, 8, wmma::precision::tf32, wmma::col_major> bf;
                    wmma::load_matrix_sync(bf, Wb + kk, 1032);
#pragma unroll
                    for (int i = 0; i < bf.num_elements; i++) bf.x[i] = wmma::__float_to_tf32(bf.x[i]);
                    wmma::mma_sync(acc[(kk >> 3) & 1], af, bf, acc[(kk >> 3) & 1]);
                }
            }
            __syncthreads();
#undef H_STAGE
#undef CHUNK_WAIT
        }

        // sum local accumulators; store K-half partial
#pragma unroll
        for (int i = 0; i < acc[0].num_elements; i++) acc[0].x[i] += acc[1].x[i];
        wmma::store_matrix_sync(&Gs[(wm * 16) * 72 + wk * 36 + wn * 16], acc[0], 72,
                                wmma::mem_row_major);
        __syncthreads();

        // ---- LSTM cell epilogue ----
        {
            float gi = Gs[eb * 72 + eu]      + Gs[eb * 72 + 36 + eu]      + x_i;
            float gf = Gs[eb * 72 + 8 + eu]  + Gs[eb * 72 + 36 + 8 + eu]  + x_f;
            float go = Gs[eb * 72 + 16 + eu] + Gs[eb * 72 + 36 + 16 + eu] + x_o;
            float gc = Gs[eb * 72 + 24 + eu] + Gs[eb * 72 + 36 + 24 + eu] + x_c;
            float si = 1.f / (1.f + expf(-gi));
            float sf = 1.f / (1.f + expf(-gf));
            float so = 1.f / (1.f + expf(-go));
            float cn = sf * cs[tid] + si * tanhf(gc);
            cs[tid] = cn;
            Htraj[(size_t)t * BH + (size_t)eb * HIDN + j0 + eu] = so * tanhf(cn);
        }

        // prefetch next step's x
        if (t + 1 < TT) {
            const float* xb = Xp + (size_t)(t + 1) * BSZ * H4 + (size_t)eb * H4 + j0 + eu;
            x_i = xb[0]; x_f = xb[HIDN]; x_o = xb[2 * HIDN]; x_c = xb[3 * HIDN];
        }

        // ---- publish h(t): release-increment this CTA's chunk counter ----
        __syncthreads();   // all h stores of this CTA done (happens-before tid0's release)
        if (tid == 0) {
            asm volatile("red.release.gpu.global.add.u32 [%0], %1;"
                         :: "l"(g_cnt + t * NCHUNK + mychunk), "r"(1u) : "memory");
        }
    }

    // ---- final cell state ----
    gC[(size_t)eb * HIDN + j0 + eu] = cs[tid];
}

// ---------------- finalize: Hf / Cf ----------------
__global__ void finalize_kernel(const float* __restrict__ h0_last,
                                const float* __restrict__ h1_last,
                                float* __restrict__ Hf,
                                float* __restrict__ Cf) {
    int i = blockIdx.x * blockDim.x + threadIdx.x;
    if (i < BH) {
        Hf[i]      = h0_last[i];
        Hf[BH + i] = h1_last[i];
        Cf[i]      = g_c[0][i];
        Cf[BH + i] = g_c[1][i];
    }
}

// ---------------- launch ----------------
extern "C" void kernel_launch(void* const* d_in, const int* in_sizes, int n_in,
                              void* d_out, int out_size) {
    const float* X    = (const float*)d_in[0]; // [T, B, D]
    const float* Wx   = (const float*)d_in[1]; // [L, 4H, D]
    const float* Wh   = (const float*)d_in[2]; // [L, 4H, H]
    const float* bias = (const float*)d_in[3]; // [L, 4H]

    float* out     = (float*)d_out;
    float* outputs = out;                              // [T, B, H]
    float* Hf      = out + (size_t)TT * BSZ * HIDN;
    float* Cf      = Hf + (size_t)NL * BH;

    float *Xp_p = nullptr, *H0_p = nullptr, *gc_p = nullptr;
    cudaGetSymbolAddress((void**)&Xp_p, g_Xp);
    cudaGetSymbolAddress((void**)&H0_p, g_H0);
    cudaGetSymbolAddress((void**)&gc_p, g_c);

    static bool attr_set = false;
    if (!attr_set) {
        cudaFuncSetAttribute(lstm_seq_kernel,
                             cudaFuncAttributeMaxDynamicSharedMemorySize,
                             SM_FLOATS * sizeof(float));
        cudaFuncSetAttribute(gemm_xp_kernel,
                             cudaFuncAttributeMaxDynamicSharedMemorySize,
                             2 * GX_BUF_FLOATS * sizeof(float));
        attr_set = true;
    }

    dim3 gg(H4 / 64, MTOT / 128);
    size_t gx_smem = 2 * GX_BUF_FLOATS * sizeof(float);
    int cnt_blocks = (TT * NCHUNK + 255) / 256;

    // Leading shim launch keeps ncu's -s index landing on lstm_seq_kernel.
    reset_cnt_kernel<<<cnt_blocks, 256>>>();

    // Layer 0
    gemm_xp_kernel<<<gg, 256, gx_smem>>>(X, Wx, bias, MTOT, H4, DIN);
    reset_cnt_kernel<<<cnt_blocks, 256>>>();
    lstm_seq_kernel<<<NCTA, NTHR, SM_FLOATS * sizeof(float)>>>(
        Wh, Xp_p, H0_p, gc_p);

    // Layer 1
    gemm_xp_kernel<<<gg, 256, gx_smem>>>(H0_p, Wx + (size_t)H4 * DIN, bias + H4, MTOT, H4, HIDN);
    reset_cnt_kernel<<<cnt_blocks, 256>>>();
    lstm_seq_kernel<<<NCTA, NTHR, SM_FLOATS * sizeof(float)>>>(
        Wh + (size_t)H4 * HIDN, Xp_p, outputs, gc_p + BH);

    finalize_kernel<<<(BH + 255) / 256, 256>>>(
        H0_p + (size_t)(TT - 1) * BH,
        outputs + (size_t)(TT - 1) * BH,
        Hf, Cf);
}

// round 11
// speedup vs baseline: 1.1592x; 1.1024x over previous
#include <cuda_runtime.h>
#include <cuda_pipeline.h>
#include <mma.h>
#include <math.h>

using namespace nvcuda;

// Problem constants
#define TT    256
#define BSZ   64
#define DIN   1024
#define HIDN  1024
#define NL    2
#define H4    (4 * HIDN)
#define MTOT  (TT * BSZ)          // 16384
#define BH    (BSZ * HIDN)        // 65536

#define NCTA  128                 // persistent CTAs, 1 per SM
#define UPC   8                   // hidden units per CTA; 32 gate-cols per CTA
#define NTHR  512                 // 16 warps: 2 K-halves x 4 batch-tiles x 2 col-tiles

// ---------------- device scratch (no allocations allowed) ----------------
__device__ float g_Xp[(size_t)MTOT * H4];   // precomputed x@Wx^T + b
__device__ float g_H0[(size_t)MTOT * HIDN]; // layer-0 hidden outputs
__device__ float g_c[NL][BH];               // final cell states
__device__ unsigned g_bar;                  // grid barrier counter

__global__ void reset_bar_kernel() {
    if (threadIdx.x == 0) g_bar = 0u;
}

// fast helpers
__device__ __forceinline__ float tf32r(float x) {
    float r;
    asm("cvt.rna.tf32.f32 %0, %1;" : "=f"(r) : "f"(x));
    return r;
}
__device__ __forceinline__ float tanh_fast(float x) {
    float r;
    asm("tanh.approx.f32 %0, %1;" : "=f"(r) : "f"(x));
    return r;
}
__device__ __forceinline__ float sig_fast(float x) {
    return fmaf(tanh_fast(0.5f * x), 0.5f, 0.5f);
}

// ---------------- precompute GEMM: C = A[M,K] @ W[N,K]^T + bias[N] -> g_Xp ----------------
// 128x64 block tile, 256 threads (8 warps: 4m x 2n, each 32x32), K-chunk 32,
// double-buffered cp.async staging. (proven R8 version)
#define GX_BUF_FLOATS ((128 + 64) * 36)

__global__ void __launch_bounds__(256, 2)
gemm_xp_kernel(const float* __restrict__ A,
               const float* __restrict__ W,
               const float* __restrict__ bias,
               int M, int N, int K) {
    extern __shared__ float gsm[];

    const int tid  = threadIdx.x;
    const int warp = tid >> 5;
    const int wm   = warp & 3;
    const int wn   = warp >> 2;
    const int row0A = blockIdx.y * 128;
    const int row0W = blockIdx.x * 64;

    wmma::fragment<wmma::accumulator, 16, 16, 8, float> acc[2][2];
#pragma unroll
    for (int i = 0; i < 2; i++)
#pragma unroll
        for (int j = 0; j < 2; j++) wmma::fill_fragment(acc[i][j], 0.f);

    const int nchunks = K / 32;

#define GX_STAGE(buf, kt)                                                          \
    {                                                                              \
        float* As_ = gsm + (buf) * GX_BUF_FLOATS;                                  \
        float* Ws_ = As_ + 128 * 36;                                               \
        int k0_ = (kt) * 32;                                                       \
        _Pragma("unroll")                                                          \
        for (int i_ = 0; i_ < 4; i_++) {                                           \
            int e_ = tid + i_ * 256;                                               \
            int r_ = e_ >> 3, c4_ = (e_ & 7) * 4;                                  \
            __pipeline_memcpy_async(&As_[r_ * 36 + c4_],                           \
                A + (size_t)(row0A + r_) * K + k0_ + c4_, 16);                     \
        }                                                                          \
        _Pragma("unroll")                                                          \
        for (int i_ = 0; i_ < 2; i_++) {                                           \
            int e_ = tid + i_ * 256;                                               \
            int r_ = e_ >> 3, c4_ = (e_ & 7) * 4;                                  \
            __pipeline_memcpy_async(&Ws_[r_ * 36 + c4_],                           \
                W + (size_t)(row0W + r_) * K + k0_ + c4_, 16);                     \
        }                                                                          \
    }

    GX_STAGE(0, 0);
    __pipeline_commit();

    for (int kt = 0; kt < nchunks; kt++) {
        int cur = kt & 1;
        __pipeline_wait_prior(0);
        __syncthreads();
        if (kt + 1 < nchunks) {
            GX_STAGE(cur ^ 1, kt + 1);
            __pipeline_commit();
        }
        float* As_ = gsm + cur * GX_BUF_FLOATS;
        float* Ws_ = As_ + 128 * 36;
#pragma unroll
        for (int kk = 0; kk < 32; kk += 8) {
            wmma::fragment<wmma::matrix_a, 16, 16, 8, wmma::precision::tf32, wmma::row_major> af[2];
            wmma::fragment<wmma::matrix_b, 16, 16, 8, wmma::precision::tf32, wmma::col_major> bf[2];
#pragma unroll
            for (int i = 0; i < 2; i++) {
                wmma::load_matrix_sync(af[i], &As_[(wm * 32 + i * 16) * 36 + kk], 36);
#pragma unroll
                for (int e = 0; e < af[i].num_elements; e++) af[i].x[e] = wmma::__float_to_tf32(af[i].x[e]);
            }
#pragma unroll
            for (int j = 0; j < 2; j++) {
                wmma::load_matrix_sync(bf[j], &Ws_[(wn * 32 + j * 16) * 36 + kk], 36);
#pragma unroll
                for (int e = 0; e < bf[j].num_elements; e++) bf[j].x[e] = wmma::__float_to_tf32(bf[j].x[e]);
            }
#pragma unroll
            for (int i = 0; i < 2; i++)
#pragma unroll
                for (int j = 0; j < 2; j++)
                    wmma::mma_sync(acc[i][j], af[i], bf[j], acc[i][j]);
        }
        __syncthreads();
    }

    float* Cs = gsm;
    __syncthreads();
#pragma unroll
    for (int i = 0; i < 2; i++)
#pragma unroll
        for (int j = 0; j < 2; j++)
            wmma::store_matrix_sync(&Cs[(wm * 32 + i * 16) * 68 + wn * 32 + j * 16],
                                    acc[i][j], 68, wmma::mem_row_major);
    __syncthreads();

    for (int idx = tid; idx < 128 * 64; idx += 256) {
        int r = idx >> 6, c = idx & 63;
        g_Xp[(size_t)(row0A + r) * N + row0W + c] = Cs[r * 68 + c] + bias[row0W + c];
    }
#undef GX_STAGE
}

// ---------------- persistent recurrence (R8 skeleton + instruction diet) ----
// 128 CTAs x 512 threads. CTA owns 8 hidden units (32 gate-cols). Wh slice in
// SMEM (132 KB, loaded once, PRE-ROUNDED TO TF32). h values stored tf32-rounded
// so mainloop needs NO per-fragment conversions: LDS + HMMA only.
// h(t-1) staged per step as 8 cp.async double-buffered chunks, order rotated
// by blockIdx. Single-counter release/acquire grid barrier between steps.
//
// SMEM floats:
//   Ws : 32 x 1032                = 33024
//   Hs : 2 x (64 x 132)           = 16896
//   Gs : 64 x 72                  =  4608
//   cs : 512                      =   512
#define SM_WS 0
#define SM_HS (SM_WS + 32 * 1032)
#define SM_GS (SM_HS + 2 * 64 * 132)
#define SM_CS (SM_GS + 64 * 72)
#define SM_FLOATS (SM_CS + 512)

__global__ void __launch_bounds__(NTHR, 1)
lstm_seq_kernel(const float* __restrict__ Wh,   // [H4, HIDN] layer base
                const float* __restrict__ Xp,   // [TT, BSZ, H4]
                float* Htraj,                   // [TT, BSZ, HIDN]
                float* __restrict__ gC) {       // [BSZ, HIDN] final cell out
    extern __shared__ float sm[];
    float* Ws = sm + SM_WS;
    float* Hs = sm + SM_HS;
    float* Gs = sm + SM_GS;
    float* cs = sm + SM_CS;

    const int tid  = threadIdx.x;
    const int warp = tid >> 5;
    const int wk   = warp >> 3;        // 0..1 K-half of each 128 chunk
    const int wm   = (warp >> 1) & 3;  // 0..3 batch tile
    const int wn   = warp & 1;         // 0..1 col tile
    const int bid  = blockIdx.x;
    const int j0   = bid * UPC;

    // ---- preload Wh slice, PRE-ROUNDED to tf32 ----
    for (int i4 = tid; i4 < 32 * 256; i4 += NTHR) {
        int n  = i4 >> 8;
        int c4 = (i4 & 255) * 4;
        int row = (n >> 3) * HIDN + j0 + (n & 7);
        float4 v = *(const float4*)(Wh + (size_t)row * HIDN + c4);
        v.x = tf32r(v.x); v.y = tf32r(v.y); v.z = tf32r(v.z); v.w = tf32r(v.w);
        *(float4*)&Ws[n * 1032 + c4] = v;
    }
    cs[tid] = 0.f;
    __syncthreads();

    // staging mapping: chunk = 64 rows x 32 float4; 512 threads -> 4 float4 each
    const int srow = tid >> 3;
    const int sc4  = (tid & 7) * 4;

    // epilogue mapping
    const int eb = tid >> 3;
    const int eu = tid & 7;

    const float* Ws_warp = Ws + (size_t)(wn * 16) * 1032;

    // x prefetch for t=0
    float x_i, x_f, x_o, x_c;
    {
        const float* xb = Xp + (size_t)eb * H4 + j0 + eu;
        x_i = xb[0]; x_f = xb[HIDN]; x_o = xb[2 * HIDN]; x_c = xb[3 * HIDN];
    }

    for (int t = 0; t < TT; t++) {
        wmma::fragment<wmma::accumulator, 16, 16, 8, float> acc[2];
        wmma::fill_fragment(acc[0], 0.f);
        wmma::fill_fragment(acc[1], 0.f);

        if (t > 0) {
            const float* Hprev = Htraj + (size_t)(t - 1) * BH;

#define H_STAGE(buf, chunk)                                                       \
            {                                                                     \
                float* Hb_ = Hs + (buf) * (64 * 132);                             \
                int k0_ = (chunk) * 128;                                          \
                _Pragma("unroll")                                                 \
                for (int p_ = 0; p_ < 4; p_++)                                    \
                    __pipeline_memcpy_async(&Hb_[srow * 132 + p_ * 32 + sc4],     \
                        Hprev + (size_t)srow * HIDN + k0_ + p_ * 32 + sc4, 16);   \
            }

            int pc0 = bid & 7;
            H_STAGE(0, pc0);
            __pipeline_commit();

            for (int it = 0; it < 8; it++) {
                int cur = it & 1;
                int pc  = (it + bid) & 7;
                __pipeline_wait_prior(0);
                __syncthreads();
                if (it < 7) {
                    int pn = (it + 1 + bid) & 7;
                    H_STAGE(cur ^ 1, pn);
                    __pipeline_commit();
                }
                const float* Hb = Hs + cur * (64 * 132);
                const float* Wb = Ws_warp + pc * 128 + wk * 64;
                const float* Ab = Hb + (wm * 16) * 132 + wk * 64;
#pragma unroll
                for (int kk = 0; kk < 64; kk += 8) {
                    wmma::fragment<wmma::matrix_a, 16, 16, 8, wmma::precision::tf32, wmma::row_major> af;
                    wmma::load_matrix_sync(af, Ab + kk, 132);
                    wmma::fragment<wmma::matrix_b, 16, 16, 8, wmma::precision::tf32, wmma::col_major> bf;
                    wmma::load_matrix_sync(bf, Wb + kk, 1032);
                    // operands are pre-rounded to tf32 — no conversion loops
                    wmma::mma_sync(acc[(kk >> 3) & 1], af, bf, acc[(kk >> 3) & 1]);
                }
            }
            __syncthreads();
#undef H_STAGE
        }

        // sum local accumulators; store K-half partial
#pragma unroll
        for (int i = 0; i < acc[0].num_elements; i++) acc[0].x[i] += acc[1].x[i];
        wmma::store_matrix_sync(&Gs[(wm * 16) * 72 + wk * 36 + wn * 16], acc[0], 72,
                                wmma::mem_row_major);
        __syncthreads();

        // ---- LSTM cell epilogue (fast tanh-based activations) ----
        {
            float gi = Gs[eb * 72 + eu]      + Gs[eb * 72 + 36 + eu]      + x_i;
            float gf = Gs[eb * 72 + 8 + eu]  + Gs[eb * 72 + 36 + 8 + eu]  + x_f;
            float go = Gs[eb * 72 + 16 + eu] + Gs[eb * 72 + 36 + 16 + eu] + x_o;
            float gc = Gs[eb * 72 + 24 + eu] + Gs[eb * 72 + 36 + 24 + eu] + x_c;
            float si = sig_fast(gi);
            float sf = sig_fast(gf);
            float so = sig_fast(go);
            float cn = fmaf(sf, cs[tid], si * tanh_fast(gc));
            cs[tid] = cn;
            // store tf32-rounded so next step's A operand needs no conversion
            Htraj[(size_t)t * BH + (size_t)eb * HIDN + j0 + eu] = tf32r(so * tanh_fast(cn));
        }

        // prefetch next step's x (overlaps the barrier)
        if (t + 1 < TT) {
            const float* xb = Xp + (size_t)(t + 1) * BSZ * H4 + (size_t)eb * H4 + j0 + eu;
            x_i = xb[0]; x_f = xb[HIDN]; x_o = xb[2 * HIDN]; x_c = xb[3 * HIDN];
        }

        // ---- single-counter grid barrier (release/acquire) ----
        __syncthreads();
        if (tid == 0) {
            asm volatile("red.release.gpu.global.add.u32 [%0], %1;"
                         :: "l"(&g_bar), "r"(1u) : "memory");
            unsigned target = (unsigned)(t + 1) * NCTA;
            unsigned v;
            do {
                asm volatile("ld.acquire.gpu.global.u32 %0, [%1];"
                             : "=r"(v) : "l"(&g_bar) : "memory");
            } while (v < target);
        }
        __syncthreads();
    }

    // ---- final cell state ----
    gC[(size_t)eb * HIDN + j0 + eu] = cs[tid];
}

// ---------------- finalize: Hf / Cf ----------------
__global__ void finalize_kernel(const float* __restrict__ h0_last,
                                const float* __restrict__ h1_last,
                                float* __restrict__ Hf,
                                float* __restrict__ Cf) {
    int i = blockIdx.x * blockDim.x + threadIdx.x;
    if (i < BH) {
        Hf[i]      = h0_last[i];
        Hf[BH + i] = h1_last[i];
        Cf[i]      = g_c[0][i];
        Cf[BH + i] = g_c[1][i];
    }
}

// ---------------- launch ----------------
extern "C" void kernel_launch(void* const* d_in, const int* in_sizes, int n_in,
                              void* d_out, int out_size) {
    const float* X    = (const float*)d_in[0]; // [T, B, D]
    const float* Wx   = (const float*)d_in[1]; // [L, 4H, D]
    const float* Wh   = (const float*)d_in[2]; // [L, 4H, H]
    const float* bias = (const float*)d_in[3]; // [L, 4H]

    float* out     = (float*)d_out;
    float* outputs = out;                              // [T, B, H]
    float* Hf      = out + (size_t)TT * BSZ * HIDN;
    float* Cf      = Hf + (size_t)NL * BH;

    float *Xp_p = nullptr, *H0_p = nullptr, *gc_p = nullptr;
    cudaGetSymbolAddress((void**)&Xp_p, g_Xp);
    cudaGetSymbolAddress((void**)&H0_p, g_H0);
    cudaGetSymbolAddress((void**)&gc_p, g_c);

    static bool attr_set = false;
    if (!attr_set) {
        cudaFuncSetAttribute(lstm_seq_kernel,
                             cudaFuncAttributeMaxDynamicSharedMemorySize,
                             SM_FLOATS * sizeof(float));
        cudaFuncSetAttribute(gemm_xp_kernel,
                             cudaFuncAttributeMaxDynamicSharedMemorySize,
                             2 * GX_BUF_FLOATS * sizeof(float));
        attr_set = true;
    }

    dim3 gg(H4 / 64, MTOT / 128);
    size_t gx_smem = 2 * GX_BUF_FLOATS * sizeof(float);

    // Leading shim launch keeps ncu's -s index landing on lstm_seq_kernel.
    reset_bar_kernel<<<1, 32>>>();

    // Layer 0
    gemm_xp_kernel<<<gg, 256, gx_smem>>>(X, Wx, bias, MTOT, H4, DIN);
    reset_bar_kernel<<<1, 32>>>();
    lstm_seq_kernel<<<NCTA, NTHR, SM_FLOATS * sizeof(float)>>>(
        Wh, Xp_p, H0_p, gc_p);

    // Layer 1
    gemm_xp_kernel<<<gg, 256, gx_smem>>>(H0_p, Wx + (size_t)H4 * DIN, bias + H4, MTOT, H4, HIDN);
    reset_bar_kernel<<<1, 32>>>();
    lstm_seq_kernel<<<NCTA, NTHR, SM_FLOATS * sizeof(float)>>>(
        Wh + (size_t)H4 * HIDN, Xp_p, outputs, gc_p + BH);

    finalize_kernel<<<(BH + 255) / 256, 256>>>(
        H0_p + (size_t)(TT - 1) * BH,
        outputs + (size_t)(TT - 1) * BH,
        Hf, Cf);
}